// round 15
// baseline (speedup 1.0000x reference)
#include <cuda_runtime.h>
#include <math.h>

constexpr int BSZ = 32, SEQ = 243, DIM = 544, NH = 8, HD = 68, NS = 17;
constexpr int TOK = BSZ * SEQ;            // 7776
constexpr int D3  = 3 * DIM;              // 1632
constexpr int M1  = 4 * DIM;              // 2176
constexpr int M2  = 2 * DIM;              // 1088
constexpr int UD  = 2 * DIM;              // 1088
constexpr int UC  = UD / NH;              // 136
constexpr int BT  = 2 * SEQ - 1;          // 485
constexpr float ATT_SCALE = 0.12126781251816648f;   // 68^-0.5

// device scratch (allocation-free rule)
__device__ float g_H  [(size_t)TOK * DIM];
__device__ float g_QKV[(size_t)TOK * D3];
__device__ float g_O  [(size_t)TOK * DIM];
__device__ float g_X  [(size_t)TOK * DIM];
__device__ float g_BIG[(size_t)TOK * M1];
__device__ float g_SA [(size_t)BSZ * NH * SEQ * NS];
__device__ float g_S0 [NS * UD];
__device__ float g_S1 [NS * UD];

__device__ __forceinline__ float gelu_f(float x) {
    return 0.5f * x * (1.0f + erff(x * 0.70710678118654752f));
}
template<int EPI>
__device__ __forceinline__ float fin(float a, float b, float r) {
    float v = a;
    if (EPI >= 1) v += b;
    if (EPI == 2) v = gelu_f(v);
    if (EPI == 3) v += r;
    return v;
}

// ---------------- layernorm: one warp / token, exact two-pass variance ----------------
__global__ void __launch_bounds__(256) ln_kernel(
    const float* __restrict__ X, const float* __restrict__ g,
    const float* __restrict__ bta, float* __restrict__ Y)
{
    int warp = (blockIdx.x * blockDim.x + threadIdx.x) >> 5;
    int lane = threadIdx.x & 31;
    if (warp >= TOK) return;
    const float* x = X + (size_t)warp * DIM;
    float v[17], s = 0.f;
#pragma unroll
    for (int k = 0; k < 17; k++) { v[k] = x[lane + 32 * k]; s += v[k]; }
#pragma unroll
    for (int o = 16; o; o >>= 1) s += __shfl_xor_sync(0xffffffffu, s, o);
    float m = s * (1.f / DIM);
    float sq = 0.f;
#pragma unroll
    for (int k = 0; k < 17; k++) { float d = v[k] - m; sq += d * d; }
#pragma unroll
    for (int o = 16; o; o >>= 1) sq += __shfl_xor_sync(0xffffffffu, sq, o);
    float r = rsqrtf(sq * (1.f / DIM) + 1e-5f);
    float* y = Y + (size_t)warp * DIM;
#pragma unroll
    for (int k = 0; k < 17; k++) {
        int c = lane + 32 * k;
        y[c] = (v[k] - m) * r * g[c] + bta[c];
    }
}

// ------------- scalar-FFMA SGEMM: C = A(TxK) @ W(JxK)^T, optional bias/gelu/residual -------------
template<int EPI>
__global__ void __launch_bounds__(256, 2) gemm_tn(
    const float* __restrict__ A, const float* __restrict__ W,
    const float* __restrict__ bias, const float* __restrict__ res,
    float* __restrict__ C, int Tn, int Jn, int Kn)
{
    __shared__ float As[8][128];
    __shared__ float Ws[8][128];

    const int tid = threadIdx.x;
    const int bm = blockIdx.y * 128, bn = blockIdx.x * 128;
    const int tx = tid & 15, ty = tid >> 4;
    const int row0 = ty * 4, col0 = tx * 4;
    const int ldr = tid >> 1, ldk = (tid & 1) * 4;

    const float* Ap = A + (size_t)(bm + ldr) * Kn + ldk;
    const float* Wp = W + (size_t)(bn + ldr) * Kn + ldk;
    const bool aok = (bm + ldr) < Tn;
    const bool wok = (bn + ldr) < Jn;

    float4 av = make_float4(0,0,0,0), wv = av;
    if (aok) av = *(const float4*)Ap;
    if (wok) wv = *(const float4*)Wp;

    float acc[8][8];
#pragma unroll
    for (int r = 0; r < 8; r++)
#pragma unroll
        for (int c = 0; c < 8; c++) acc[r][c] = 0.f;

    for (int k0 = 0; k0 < Kn; k0 += 8) {
        __syncthreads();
        As[ldk+0][ldr] = av.x; As[ldk+1][ldr] = av.y;
        As[ldk+2][ldr] = av.z; As[ldk+3][ldr] = av.w;
        Ws[ldk+0][ldr] = wv.x; Ws[ldk+1][ldr] = wv.y;
        Ws[ldk+2][ldr] = wv.z; Ws[ldk+3][ldr] = wv.w;
        __syncthreads();
        int k1 = k0 + 8;
        if (k1 < Kn) {
            if (aok) av = *(const float4*)(Ap + k1);
            if (wok) wv = *(const float4*)(Wp + k1);
        }
#pragma unroll
        for (int kk = 0; kk < 8; kk++) {
            float4 a0 = *(const float4*)&As[kk][row0];
            float4 a1 = *(const float4*)&As[kk][row0 + 64];
            float4 w0 = *(const float4*)&Ws[kk][col0];
            float4 w1 = *(const float4*)&Ws[kk][col0 + 64];
            float ar[8] = { a0.x, a0.y, a0.z, a0.w, a1.x, a1.y, a1.z, a1.w };
            float wr[8] = { w0.x, w0.y, w0.z, w0.w, w1.x, w1.y, w1.z, w1.w };
#pragma unroll
            for (int r = 0; r < 8; r++)
#pragma unroll
                for (int c = 0; c < 8; c++)
                    acc[r][c] = fmaf(ar[r], wr[c], acc[r][c]);
        }
    }

    const bool c0ok = (bn + col0) < Jn;
    const bool c1ok = (bn + col0 + 64) < Jn;
    float4 bv0 = make_float4(0,0,0,0), bv1 = bv0;
    if (EPI >= 1) {
        if (c0ok) bv0 = *(const float4*)(bias + bn + col0);
        if (c1ok) bv1 = *(const float4*)(bias + bn + col0 + 64);
    }
#pragma unroll
    for (int rh = 0; rh < 2; rh++) {
#pragma unroll
        for (int ri = 0; ri < 4; ri++) {
            int m = bm + rh * 64 + row0 + ri;
            if (m >= Tn) continue;
            int r = rh * 4 + ri;
            if (c0ok) {
                float4 rv = make_float4(0,0,0,0);
                if (EPI == 3) rv = *(const float4*)(res + (size_t)m * Jn + bn + col0);
                float4 o;
                o.x = fin<EPI>(acc[r][0], bv0.x, rv.x);
                o.y = fin<EPI>(acc[r][1], bv0.y, rv.y);
                o.z = fin<EPI>(acc[r][2], bv0.z, rv.z);
                o.w = fin<EPI>(acc[r][3], bv0.w, rv.w);
                *(float4*)(C + (size_t)m * Jn + bn + col0) = o;
            }
            if (c1ok) {
                float4 rv = make_float4(0,0,0,0);
                if (EPI == 3) rv = *(const float4*)(res + (size_t)m * Jn + bn + col0 + 64);
                float4 o;
                o.x = fin<EPI>(acc[r][4], bv1.x, rv.x);
                o.y = fin<EPI>(acc[r][5], bv1.y, rv.y);
                o.z = fin<EPI>(acc[r][6], bv1.z, rv.z);
                o.w = fin<EPI>(acc[r][7], bv1.w, rv.w);
                *(float4*)(C + (size_t)m * Jn + bn + col0 + 64) = o;
            }
        }
    }
}

// ---------------- attention: block per (b,h), warp per row, HD = 68 ----------------
constexpr int AT_S = 72;                   // padded row stride (floats)
constexpr int SM_KV = SEQ * AT_S;          // 17496
constexpr int ATT_SMEM_BYTES = (2 * SM_KV + 8 * 256 + 8 * AT_S) * 4;  // ~150 KB

__global__ void __launch_bounds__(256, 1) attn_kernel(
    const float* __restrict__ qkv, const float* __restrict__ b_table,
    float* __restrict__ O)
{
    extern __shared__ float sm[];
    float* Ks = sm;
    float* Vs = Ks + SM_KV;
    float* Ps = Vs + SM_KV;            // 8 warps * 256
    float* Qs = Ps + 8 * 256;          // 8 warps * AT_S

    const int bh = blockIdx.x, b = bh >> 3, h = bh & 7;
    const float* base = qkv + (size_t)b * SEQ * D3 + h * HD;
    const int tid = threadIdx.x, warp = tid >> 5, lane = tid & 31;

    // stage K, V rows [SEQ][68] (17 float4 per row)
    for (int idx = tid; idx < SEQ * 17; idx += 256) {
        int j = idx / 17, q4 = (idx % 17) * 4;
        const float* rp = base + (size_t)j * D3 + q4;
        *(float4*)(Ks + j * AT_S + q4) = *(const float4*)(rp + DIM);
        *(float4*)(Vs + j * AT_S + q4) = *(const float4*)(rp + 2 * DIM);
    }
    __syncthreads();

    const float* bt = b_table + h * BT + (SEQ - 1);   // bt[i - j]
    float* Pw = Ps + warp * 256;
    float* Qw = Qs + warp * AT_S;

    for (int i = warp; i < SEQ; i += 8) {
        // stage q row i (68 floats)
        Qw[lane]      = base[(size_t)i * D3 + lane];
        Qw[lane + 32] = base[(size_t)i * D3 + lane + 32];
        if (lane < 4) Qw[lane + 64] = base[(size_t)i * D3 + lane + 64];
        __syncwarp();

        float p[8], mx = -1e30f;
#pragma unroll
        for (int jj = 0; jj < 8; jj++) {
            int j = jj * 32 + lane;
            float sv = -1e30f;
            if (j < SEQ) {
                const float* kr = Ks + j * AT_S;
                float acc = 0.f;
#pragma unroll
                for (int d = 0; d < HD; d += 4) {
                    float4 qv = *(const float4*)(Qw + d);
                    float4 kv = *(const float4*)(kr + d);
                    acc = fmaf(qv.x, kv.x, acc);
                    acc = fmaf(qv.y, kv.y, acc);
                    acc = fmaf(qv.z, kv.z, acc);
                    acc = fmaf(qv.w, kv.w, acc);
                }
                sv = acc * ATT_SCALE + bt[i - j];
            }
            p[jj] = sv;
            mx = fmaxf(mx, sv);
        }
#pragma unroll
        for (int o = 16; o; o >>= 1)
            mx = fmaxf(mx, __shfl_xor_sync(0xffffffffu, mx, o));
        float sum = 0.f;
#pragma unroll
        for (int jj = 0; jj < 8; jj++) {
            int j = jj * 32 + lane;
            float e = (j < SEQ) ? expf(p[jj] - mx) : 0.f;
            p[jj] = e; sum += e;
        }
#pragma unroll
        for (int o = 16; o; o >>= 1)
            sum += __shfl_xor_sync(0xffffffffu, sum, o);
        float inv = 1.f / sum;
#pragma unroll
        for (int jj = 0; jj < 8; jj++)
            Pw[jj * 32 + lane] = p[jj] * inv;
        __syncwarp();

        // o[d] = sum_j P[j] * V[j][d]; lane owns d = lane, lane+32, (lane<4) lane+64
        float o0 = 0.f, o1 = 0.f, o2 = 0.f;
        for (int j = 0; j < SEQ; j++) {
            float pj = Pw[j];
            const float* vr = Vs + j * AT_S;
            o0 = fmaf(pj, vr[lane],               o0);
            o1 = fmaf(pj, vr[lane + 32],          o1);
            o2 = fmaf(pj, vr[64 + (lane & 3)],    o2);
        }
        float* orow = O + (size_t)(b * SEQ + i) * DIM + h * HD;
        orow[lane]      = o0;
        orow[lane + 32] = o1;
        if (lane < 4) orow[lane + 64] = o2;
        __syncwarp();
    }
}

// ---------------- seed projection: one warp per output column ----------------
__global__ void __launch_bounds__(256) seed_gemm(
    const float* __restrict__ seed, const float* __restrict__ W,
    const float* __restrict__ bias, float* __restrict__ out)
{
    int j = (blockIdx.x * blockDim.x + threadIdx.x) >> 5;
    int lane = threadIdx.x & 31;
    if (j >= UD) return;
    const float* w = W + (size_t)j * DIM;
    float acc[NS];
#pragma unroll
    for (int n = 0; n < NS; n++) acc[n] = 0.f;
    for (int kk = 0; kk < 17; kk++) {
        int k = lane + 32 * kk;
        float wv = w[k];
#pragma unroll
        for (int n = 0; n < NS; n++) acc[n] = fmaf(wv, seed[n * DIM + k], acc[n]);
    }
#pragma unroll
    for (int n = 0; n < NS; n++)
#pragma unroll
        for (int o = 16; o; o >>= 1)
            acc[n] += __shfl_xor_sync(0xffffffffu, acc[n], o);
    if (lane == 0) {
        float bv = bias[j];
#pragma unroll
        for (int n = 0; n < NS; n++) out[n * UD + j] = acc[n] + bv;
    }
}

// -------- a[b,h,f,n] = sum_c xu[t, h*UC+c] * s0[n, h*UC+c] --------
__global__ void __launch_bounds__(256) ext_attn_logits(
    const float* __restrict__ XU, const float* __restrict__ S0,
    float* __restrict__ SA)
{
    const int h = blockIdx.y;
    int warp = threadIdx.x >> 5, lane = threadIdx.x & 31;
    int t = blockIdx.x * 8 + warp;
    if (t >= TOK) return;
    const float* xu = XU + (size_t)t * UD + h * UC;
    float acc[NS];
#pragma unroll
    for (int n = 0; n < NS; n++) acc[n] = 0.f;
#pragma unroll
    for (int k = 0; k < 5; k++) {
        int c = lane + 32 * k;
        if (c < UC) {
            float xv = xu[c];
#pragma unroll
            for (int n = 0; n < NS; n++)
                acc[n] = fmaf(xv, S0[n * UD + h * UC + c], acc[n]);
        }
    }
#pragma unroll
    for (int n = 0; n < NS; n++)
#pragma unroll
        for (int o = 16; o; o >>= 1)
            acc[n] += __shfl_xor_sync(0xffffffffu, acc[n], o);
    if (lane == 0) {
        int b = t / SEQ, f = t % SEQ;
        float* out = SA + ((size_t)(b * NH + h) * SEQ + f) * NS;
#pragma unroll
        for (int n = 0; n < NS; n++) out[n] = acc[n];
    }
}

// softmax over f (axis=-2): one warp per (b,h,n)
__global__ void __launch_bounds__(256) ext_softmax_f(float* __restrict__ SA)
{
    int id = (blockIdx.x * blockDim.x + threadIdx.x) >> 5;
    int lane = threadIdx.x & 31;
    if (id >= BSZ * NH * NS) return;
    int bh = id / NS, n = id % NS;
    float* base = SA + (size_t)bh * SEQ * NS + n;
    float v[8], mx = -1e30f;
#pragma unroll
    for (int k = 0; k < 8; k++) {
        int f = lane + 32 * k;
        v[k] = (f < SEQ) ? base[(size_t)f * NS] : -1e30f;
        mx = fmaxf(mx, v[k]);
    }
#pragma unroll
    for (int o = 16; o; o >>= 1)
        mx = fmaxf(mx, __shfl_xor_sync(0xffffffffu, mx, o));
    float s = 0.f;
#pragma unroll
    for (int k = 0; k < 8; k++) {
        int f = lane + 32 * k;
        float e = (f < SEQ) ? expf(v[k] - mx) : 0.f;
        v[k] = e; s += e;
    }
#pragma unroll
    for (int o = 16; o; o >>= 1)
        s += __shfl_xor_sync(0xffffffffu, s, o);
    float inv = 1.f / s;
#pragma unroll
    for (int k = 0; k < 8; k++) {
        int f = lane + 32 * k;
        if (f < SEQ) base[(size_t)f * NS] = v[k] * inv;
    }
}

// a /= (1e-7 + sum_n a)
__global__ void __launch_bounds__(256) ext_norm(float* __restrict__ SA)
{
    int row = blockIdx.x * blockDim.x + threadIdx.x;
    if (row >= BSZ * NH * SEQ) return;
    float* p = SA + (size_t)row * NS;
    float v[NS], s = 0.f;
#pragma unroll
    for (int n = 0; n < NS; n++) { v[n] = p[n]; s += v[n]; }
    float inv = 1.f / (1e-7f + s);
#pragma unroll
    for (int n = 0; n < NS; n++) p[n] = v[n] * inv;
}

// mean over (b,h,f): one warp per n, deterministic
__global__ void ext_mean(const float* __restrict__ SA, float* __restrict__ out)
{
    int warp = threadIdx.x >> 5, lane = threadIdx.x & 31;
    float s = 0.f;
    for (int row = lane; row < BSZ * NH * SEQ; row += 32)
        s += SA[(size_t)row * NS + warp];
#pragma unroll
    for (int o = 16; o; o >>= 1)
        s += __shfl_xor_sync(0xffffffffu, s, o);
    if (lane == 0) out[warp] = s * (1.f / (BSZ * NH * SEQ));
}

// o2[t, h*UC+c] = sum_n a[b,h,f,n] * s1[n, h*UC+c]
__global__ void __launch_bounds__(256) ext_attn_out(
    const float* __restrict__ SA, const float* __restrict__ S1,
    float* __restrict__ O2)
{
    const int h = blockIdx.y;
    int warp = threadIdx.x >> 5, lane = threadIdx.x & 31;
    int t = blockIdx.x * 8 + warp;
    if (t >= TOK) return;
    const float* arow = SA + ((size_t)((t / SEQ) * NH + h) * SEQ + (t % SEQ)) * NS;
    float acc[5] = {0.f, 0.f, 0.f, 0.f, 0.f};
#pragma unroll
    for (int n = 0; n < NS; n++) {
        float av = arow[n];
#pragma unroll
        for (int k = 0; k < 5; k++) {
            int c = lane + 32 * k;
            if (c < UC) acc[k] = fmaf(av, S1[n * UD + h * UC + c], acc[k]);
        }
    }
#pragma unroll
    for (int k = 0; k < 5; k++) {
        int c = lane + 32 * k;
        if (c < UC) O2[(size_t)t * UD + h * UC + c] = acc[k];
    }
}

// ---------------- host ----------------
static inline dim3 ggrid(int Jn, int Tn) {
    return dim3((Jn + 127) / 128, (Tn + 127) / 128);
}

extern "C" void kernel_launch(void* const* d_in, const int* in_sizes, int n_in,
                              void* d_out, int out_size)
{
    const float* x       = (const float*)d_in[0];
    const float* seed    = (const float*)d_in[1];
    const float* ln1_g   = (const float*)d_in[2];
    const float* ln1_b   = (const float*)d_in[3];
    const float* w_qkv   = (const float*)d_in[4];
    const float* w_proj  = (const float*)d_in[5];
    const float* b_proj  = (const float*)d_in[6];
    const float* b_table = (const float*)d_in[7];
    const float* ln2_g   = (const float*)d_in[8];
    const float* ln2_b   = (const float*)d_in[9];
    const float* mlp_w1  = (const float*)d_in[10];
    const float* mlp_b1  = (const float*)d_in[11];
    const float* mlp_w2  = (const float*)d_in[12];
    const float* mlp_b2  = (const float*)d_in[13];
    const float* eln1_g  = (const float*)d_in[14];
    const float* eln1_b  = (const float*)d_in[15];
    const float* w_trans = (const float*)d_in[16];
    const float* b_trans = (const float*)d_in[17];
    const float* w0      = (const float*)d_in[18];
    const float* b0      = (const float*)d_in[19];
    const float* w1      = (const float*)d_in[20];
    const float* b1      = (const float*)d_in[21];
    const float* w_proj2 = (const float*)d_in[22];
    const float* b_proj2 = (const float*)d_in[23];
    const float* eln2_g  = (const float*)d_in[24];
    const float* eln2_b  = (const float*)d_in[25];
    const float* emlp_w1 = (const float*)d_in[26];
    const float* emlp_b1 = (const float*)d_in[27];
    const float* emlp_w2 = (const float*)d_in[28];
    const float* emlp_b2 = (const float*)d_in[29];

    float* out_x    = (float*)d_out;                       // TOK*DIM
    float* out_mean = (float*)d_out + (size_t)TOK * DIM;   // NS

    float *H, *QKV, *O, *X, *BIG, *SA, *S0, *S1;
    cudaGetSymbolAddress((void**)&H,   g_H);
    cudaGetSymbolAddress((void**)&QKV, g_QKV);
    cudaGetSymbolAddress((void**)&O,   g_O);
    cudaGetSymbolAddress((void**)&X,   g_X);
    cudaGetSymbolAddress((void**)&BIG, g_BIG);
    cudaGetSymbolAddress((void**)&SA,  g_SA);
    cudaGetSymbolAddress((void**)&S0,  g_S0);
    cudaGetSymbolAddress((void**)&S1,  g_S1);

    cudaFuncSetAttribute(attn_kernel,
        cudaFuncAttributeMaxDynamicSharedMemorySize, ATT_SMEM_BYTES);

    const int LNB = (TOK * 32 + 255) / 256;   // 972 blocks, 1 warp/token

    // ---- block 1: attention ----
    ln_kernel<<<LNB, 256>>>(x, ln1_g, ln1_b, H);
    gemm_tn<0><<<ggrid(D3, TOK), 256>>>(H, w_qkv, nullptr, nullptr, QKV, TOK, D3, DIM);
    attn_kernel<<<BSZ * NH, 256, ATT_SMEM_BYTES>>>(QKV, b_table, O);
    gemm_tn<3><<<ggrid(DIM, TOK), 256>>>(O, w_proj, b_proj, x, X, TOK, DIM, DIM);

    // ---- block 2: MLP ----
    ln_kernel<<<LNB, 256>>>(X, ln2_g, ln2_b, H);
    gemm_tn<2><<<ggrid(M1, TOK), 256>>>(H, mlp_w1, mlp_b1, nullptr, BIG, TOK, M1, DIM);
    gemm_tn<3><<<ggrid(DIM, TOK), 256>>>(BIG, mlp_w2, mlp_b2, X, X, TOK, DIM, M1);

    // ---- block 3: external (seed) attention ----
    ln_kernel<<<LNB, 256>>>(X, eln1_g, eln1_b, H);
    gemm_tn<1><<<ggrid(UD, TOK), 256>>>(H, w_trans, b_trans, nullptr, BIG, TOK, UD, DIM);
    seed_gemm<<<(UD * 32 + 255) / 256, 256>>>(seed, w0, b0, S0);
    seed_gemm<<<(UD * 32 + 255) / 256, 256>>>(seed, w1, b1, S1);
    ext_attn_logits<<<dim3((TOK + 7) / 8, NH), 256>>>(BIG, S0, SA);
    ext_softmax_f<<<(BSZ * NH * NS * 32 + 255) / 256, 256>>>(SA);
    ext_norm<<<(BSZ * NH * SEQ + 255) / 256, 256>>>(SA);
    ext_mean<<<1, NS * 32>>>(SA, out_mean);
    ext_attn_out<<<dim3((TOK + 7) / 8, NH), 256>>>(SA, S1, BIG);
    gemm_tn<3><<<ggrid(DIM, TOK), 256>>>(BIG, w_proj2, b_proj2, X, X, TOK, DIM, UD);

    // ---- block 4: final MLP -> output ----
    ln_kernel<<<LNB, 256>>>(X, eln2_g, eln2_b, H);
    gemm_tn<2><<<ggrid(M1, TOK), 256>>>(H, emlp_w1, emlp_b1, nullptr, BIG, TOK, M2, DIM);
    gemm_tn<3><<<ggrid(DIM, TOK), 256>>>(BIG, emlp_w2, emlp_b2, X, out_x, TOK, DIM, M2);
}